// round 1
// baseline (speedup 1.0000x reference)
#include <cuda_runtime.h>
#include <stdint.h>

// GazeOnce360 post-processing:
//   scores = softmax(conf)[:,1]; s = score>0.9 ? score : -1
//   top-512 (desc, index tie-break) -> decode boxes *2048 -> greedy NMS (iou>0.4)
//   out[512,5] = keep ? [box/2048, score] : 0
//
// Inputs (metadata order): loc [1,N,4] f32, conf [1,N,2] f32, priors [N,4] f32
// N = 2,097,152. Output: 512*5 f32.

#define KDET 512
#define NBINS 8192
#define BIN_BASE (0x3F666667u >> 8)   // bits of smallest score > 0.9f, >>8
#define CAND_CAP 1024

// -------- scratch (no allocations allowed) --------
__device__ unsigned int       g_hist[NBINS];
__device__ unsigned int       g_n;
__device__ unsigned int       g_B;
__device__ unsigned long long g_keys[CAND_CAP];
__device__ float4             g_cand[KDET];
__device__ float              g_score[KDET];
__device__ unsigned int       g_mask[KDET * 16];

// softmax(c0,c1)[1] exactly as jax.nn.softmax (subtract max, exp, normalize)
__device__ __forceinline__ float face_score(float c0, float c1) {
    float m  = fmaxf(c0, c1);
    float e0 = expf(c0 - m);
    float e1 = expf(c1 - m);
    return e1 / (e0 + e1);
}

// ---------------- K0: zero scratch ----------------
__global__ void k_zero() {
    int t = blockIdx.x * blockDim.x + threadIdx.x;
    if (t < NBINS) g_hist[t] = 0u;
    if (t == 0) { g_n = 0u; g_B = 0u; }
}

// ---------------- K1: histogram of candidate score bits ----------------
// Each thread handles 2 elements via one coalesced float4 load of conf.
__global__ void __launch_bounds__(512) k_hist(const float4* __restrict__ conf4,
                                              int nElem) {
    int T = blockIdx.x * blockDim.x + threadIdx.x;      // pair index
    int e = 2 * T;
    if (e >= nElem) return;
    float4 f = conf4[T];
    {
        float s = face_score(f.x, f.y);
        if (s > 0.9f)
            atomicAdd(&g_hist[(__float_as_uint(s) >> 8) - BIN_BASE], 1u);
    }
    if (e + 1 < nElem) {
        float s = face_score(f.z, f.w);
        if (s > 0.9f)
            atomicAdd(&g_hist[(__float_as_uint(s) >> 8) - BIN_BASE], 1u);
    }
}

// ---------------- K2: suffix-scan histogram, find cutoff bin ----------------
// B = max bin b with (count of candidates in bins >= b) >= 512, else 0.
__global__ void __launch_bounds__(1024) k_select() {
    __shared__ unsigned int ssum[1024];
    int t = threadIdx.x;
    unsigned int h[8];
    unsigned int p = 0;
#pragma unroll
    for (int j = 0; j < 8; j++) { h[j] = g_hist[t * 8 + j]; p += h[j]; }
    ssum[t] = p;
    __syncthreads();
    for (int off = 1; off < 1024; off <<= 1) {
        unsigned int v = (t + off < 1024) ? ssum[t + off] : 0u;
        __syncthreads();
        ssum[t] += v;
        __syncthreads();
    }
    unsigned int cum = (t < 1023) ? ssum[t + 1] : 0u;   // sum of bins >= 8(t+1)
    int best = -1;
#pragma unroll
    for (int j = 7; j >= 0; j--) {
        cum += h[j];                                    // sum of bins >= 8t+j
        if (cum >= KDET) { best = t * 8 + j; break; }
    }
    if (best >= 0) atomicMax(&g_B, (unsigned int)best);
}

// ---------------- K3: compact keys of candidates in bins >= B ----------------
__global__ void __launch_bounds__(512) k_collect(const float4* __restrict__ conf4,
                                                 int nElem) {
    int T = blockIdx.x * blockDim.x + threadIdx.x;
    int e = 2 * T;
    if (e >= nElem) return;
    unsigned int B = g_B;
    float4 f = conf4[T];
#pragma unroll
    for (int q = 0; q < 2; q++) {
        int ei = e + q;
        if (ei >= nElem) break;
        float c0 = q ? f.z : f.x;
        float c1 = q ? f.w : f.y;
        float s = face_score(c0, c1);
        if (s > 0.9f) {
            unsigned int bits = __float_as_uint(s);
            if ((bits >> 8) - BIN_BASE >= B) {
                unsigned int pos = atomicAdd(&g_n, 1u);
                if (pos < CAND_CAP)
                    g_keys[pos] = ((unsigned long long)bits << 32)
                                | (unsigned long long)(0xFFFFFFFFu - (unsigned)ei);
            }
        }
    }
}

// ---------------- K4: sort 1024 keys desc (bitonic), decode top 512 ----------
__global__ void __launch_bounds__(512) k_sortdecode(const float4* __restrict__ loc4,
                                                    const float4* __restrict__ pri4) {
    __shared__ unsigned long long sk[CAND_CAP];
    int t = threadIdx.x;
    unsigned int n = min(g_n, (unsigned int)CAND_CAP);
    for (int i = t; i < CAND_CAP; i += 512)
        sk[i] = (i < n) ? g_keys[i] : 0ULL;
    __syncthreads();

    for (int k = 2; k <= CAND_CAP; k <<= 1) {
        for (int j = k >> 1; j > 0; j >>= 1) {
            for (int i = t; i < CAND_CAP; i += 512) {
                int ixj = i ^ j;
                if (ixj > i) {
                    unsigned long long a = sk[i], b = sk[ixj];
                    bool desc = ((i & k) == 0);        // overall descending
                    if (desc ? (a < b) : (a > b)) { sk[i] = b; sk[ixj] = a; }
                }
            }
            __syncthreads();
        }
    }

    if (t < KDET) {
        unsigned long long key = sk[t];
        unsigned int sb = (unsigned int)(key >> 32);
        float4 c = make_float4(0.f, 0.f, 0.f, 0.f);
        float sc = 0.f;
        if (sb) {
            unsigned int idx = 0xFFFFFFFFu - (unsigned int)(key & 0xFFFFFFFFull);
            float4 l = loc4[idx];
            float4 p = pri4[idx];
            float cx = p.x + (l.x * 0.1f) * p.z;
            float cy = p.y + (l.y * 0.1f) * p.w;
            float w  = p.z * expf(l.z * 0.2f);
            float h  = p.w * expf(l.w * 0.2f);
            float x1 = cx - w * 0.5f;
            float y1 = cy - h * 0.5f;
            float x2 = x1 + w;
            float y2 = y1 + h;
            c = make_float4(x1 * 2048.f, y1 * 2048.f, x2 * 2048.f, y2 * 2048.f);
            sc = __uint_as_float(sb);
        }
        g_cand[t]  = c;
        g_score[t] = sc;
    }
}

// ---------------- K5: 512x512 suppression bitmask -----------------
// word w: row i = w>>4, column chunk c = w&15 covering j = 32c..32c+31
__global__ void __launch_bounds__(256) k_mask() {
    int w = blockIdx.x * blockDim.x + threadIdx.x;     // 0..8191
    int i = w >> 4, c = w & 15;
    float4 bi = g_cand[i];
    float areai = (bi.z - bi.x + 1.f) * (bi.w - bi.y + 1.f);
    unsigned int bits = 0u;
#pragma unroll 4
    for (int b = 0; b < 32; b++) {
        int j = c * 32 + b;
        float4 bj = g_cand[j];
        float areaj = (bj.z - bj.x + 1.f) * (bj.w - bj.y + 1.f);
        float xx1 = fmaxf(bi.x, bj.x), yy1 = fmaxf(bi.y, bj.y);
        float xx2 = fminf(bi.z, bj.z), yy2 = fminf(bi.w, bj.w);
        float ww = fmaxf(xx2 - xx1 + 1.f, 0.f);
        float hh = fmaxf(yy2 - yy1 + 1.f, 0.f);
        float inter = ww * hh;
        float iou = inter / (areai + areaj - inter);
        if (iou > 0.4f && j > i) bits |= (1u << b);
    }
    g_mask[w] = bits;
}

// ---------------- K6: sequential greedy NMS scan + write output ----------
__global__ void __launch_bounds__(512) k_nms_out(float* __restrict__ out) {
    __shared__ unsigned int smask[KDET * 16];
    __shared__ unsigned int skeep[16];
    int t = threadIdx.x;
    for (int i = t; i < KDET * 16; i += 512) smask[i] = g_mask[i];

    bool k0 = g_score[t] > 0.0f;                       // keep0 = top_s > 0
    unsigned int wball = __ballot_sync(0xFFFFFFFFu, k0);
    if ((t & 31) == 0) skeep[t >> 5] = wball;
    __syncthreads();

    if (t < 32) {
        // lane L (<16) owns keep bits for candidates [32L, 32L+32)
        unsigned int kw = (t < 16) ? skeep[t] : 0u;
        for (int i = 0; i < KDET; i++) {
            unsigned int ow = __shfl_sync(0xFFFFFFFFu, kw, i >> 5);
            if ((ow >> (i & 31)) & 1u) {               // row i still kept
                unsigned int m = smask[i * 16 + (t & 15)];
                if (t < 16) kw &= ~m;
            }
        }
        if (t < 16) skeep[t] = kw;
    }
    __syncthreads();

    unsigned int kept = (skeep[t >> 5] >> (t & 31)) & 1u;
    float4 c = g_cand[t];
    float sc = g_score[t];
    const float inv = 1.0f / 2048.0f;                  // exact (power of 2)
    float o0 = 0.f, o1 = 0.f, o2 = 0.f, o3 = 0.f, o4 = 0.f;
    if (kept) { o0 = c.x * inv; o1 = c.y * inv; o2 = c.z * inv; o3 = c.w * inv; o4 = sc; }
    out[t * 5 + 0] = o0;
    out[t * 5 + 1] = o1;
    out[t * 5 + 2] = o2;
    out[t * 5 + 3] = o3;
    out[t * 5 + 4] = o4;
}

extern "C" void kernel_launch(void* const* d_in, const int* in_sizes, int n_in,
                              void* d_out, int out_size) {
    const float4* loc4  = (const float4*)d_in[0];   // [N,4]
    const float4* conf4 = (const float4*)d_in[1];   // [N,2] viewed as N/2 float4
    const float4* pri4  = (const float4*)d_in[2];   // [N,4]
    float* out = (float*)d_out;

    int nElem = in_sizes[1] / 2;                    // number of priors N
    int nPairs = (nElem + 1) / 2;
    int scanBlocks = (nPairs + 511) / 512;

    k_zero<<<(NBINS + 255) / 256, 256>>>();
    k_hist<<<scanBlocks, 512>>>(conf4, nElem);
    k_select<<<1, 1024>>>();
    k_collect<<<scanBlocks, 512>>>(conf4, nElem);
    k_sortdecode<<<1, 512>>>(loc4, pri4);
    k_mask<<<(KDET * 16) / 256, 256>>>();
    k_nms_out<<<1, 512>>>(out);
}

// round 2
// speedup vs baseline: 1.1729x; 1.1729x over previous
#include <cuda_runtime.h>
#include <stdint.h>

// GazeOnce360 post-processing, round 2:
//   single fused conf scan (prefilter + exact softmax score) -> candidate buffer +
//   8192-bin histogram -> bin threshold -> compact -> bitonic top-512 sort ->
//   decode -> 512x512 suppression mask -> single-thread ffs-skip greedy NMS.
//
// Inputs: loc [1,N,4] f32, conf [1,N,2] f32, priors [N,4] f32. N=2,097,152.
// Output: [512,5] f32.

#define KDET 512
#define NBINS 8192
#define BIN_BASE (0x3F666667u >> 8)   // bits of smallest float > 0.9f, >>8
#define CAND_CAP 1024
#define ALL_CAP  262144               // ~2x expected candidate count (~126k)

// -------- scratch (no allocations allowed) --------
__device__ unsigned int       g_hist[NBINS];
__device__ unsigned int       g_n;       // total candidates appended
__device__ unsigned int       g_B;       // cutoff bin
__device__ unsigned int       g_nkeys;   // compacted key count
__device__ unsigned long long g_all[ALL_CAP];
__device__ unsigned long long g_keys[CAND_CAP];
__device__ float4             g_cand[KDET];
__device__ float              g_score[KDET];
__device__ unsigned int       g_mask[KDET * 16];

// ---------------- K0: zero scratch ----------------
__global__ void k_zero() {
    int t = blockIdx.x * blockDim.x + threadIdx.x;
    if (t < NBINS) g_hist[t] = 0u;
    if (t == 0) { g_n = 0u; g_B = 0u; g_nkeys = 0u; }
}

// ---------------- K1: fused scan: score + histogram + append candidates -------
// Each thread: 4 float4 loads (8 conf pairs), batched for MLP.
// score = softmax(c0,c1)[1]; for candidates c1>c0 so reference computes exactly
// s = 1/(exp(c0-c1)+1). Prefilter d>2.19 (< ln9) skips expf for ~94% of lanes.
__global__ void __launch_bounds__(512) k_scan(const float4* __restrict__ conf4,
                                              int nPairs) {
    int base = blockIdx.x * (512 * 4) + threadIdx.x;
    float4 f[4];
#pragma unroll
    for (int k = 0; k < 4; k++) {
        int idx = base + k * 512;
        f[k] = (idx < nPairs) ? conf4[idx] : make_float4(0.f, 0.f, 0.f, 0.f);
    }

    unsigned long long key[8];
    unsigned vmask = 0u;
#pragma unroll
    for (int k = 0; k < 4; k++) {
        int pidx = base + k * 512;
#pragma unroll
        for (int q = 0; q < 2; q++) {
            float c0 = q ? f[k].z : f[k].x;
            float c1 = q ? f[k].w : f[k].y;
            int   ei = 2 * pidx + q;
            float d  = c1 - c0;
            key[k * 2 + q] = 0ULL;
            if (d > 2.19f && pidx < nPairs) {
                float e0 = expf(c0 - c1);          // == exp(c0 - max) with e1 = 1
                float s  = 1.0f / (e0 + 1.0f);     // == e1/(e0+e1) exactly
                if (s > 0.9f) {
                    unsigned bits = __float_as_uint(s);
                    atomicAdd(&g_hist[(bits >> 8) - BIN_BASE], 1u);
                    key[k * 2 + q] = ((unsigned long long)bits << 32)
                                   | (unsigned long long)(0xFFFFFFFFu - (unsigned)ei);
                    vmask |= 1u << (k * 2 + q);
                }
            }
        }
    }

    // block-aggregated append: one global atomic per block
    int lane = threadIdx.x & 31, wid = threadIdx.x >> 5;
    int cnt = __popc(vmask);
    int pfx = cnt;
#pragma unroll
    for (int off = 1; off < 32; off <<= 1) {
        int v = __shfl_up_sync(0xFFFFFFFFu, pfx, off);
        if (lane >= off) pfx += v;
    }
    __shared__ unsigned wtot[16], wbase[16], blockbase;
    if (lane == 31) wtot[wid] = (unsigned)pfx;
    __syncthreads();
    if (threadIdx.x == 0) {
        unsigned tot = 0;
#pragma unroll
        for (int w = 0; w < 16; w++) { wbase[w] = tot; tot += wtot[w]; }
        blockbase = atomicAdd(&g_n, tot);
    }
    __syncthreads();
    unsigned p = blockbase + wbase[wid] + (unsigned)(pfx - cnt);
#pragma unroll
    for (int j = 0; j < 8; j++) {
        if (vmask & (1u << j)) {
            if (p < ALL_CAP) g_all[p] = key[j];
            p++;
        }
    }
}

// ---------------- K2: suffix-scan histogram, find cutoff bin ----------------
// B = max bin b with (count of candidates in bins >= b) >= 512, else 0.
__global__ void __launch_bounds__(512) k_select() {
    __shared__ unsigned ssum[512];
    int t = threadIdx.x;
    unsigned h[16];
    unsigned psum = 0;
#pragma unroll
    for (int j = 0; j < 16; j++) { h[j] = g_hist[t * 16 + j]; psum += h[j]; }
    ssum[t] = psum;
    __syncthreads();
    for (int off = 1; off < 512; off <<= 1) {
        unsigned v = (t + off < 512) ? ssum[t + off] : 0u;
        __syncthreads();
        ssum[t] += v;
        __syncthreads();
    }
    unsigned cum = (t < 511) ? ssum[t + 1] : 0u;   // sum of bins >= 16(t+1)
    int best = -1;
#pragma unroll
    for (int j = 15; j >= 0; j--) {
        cum += h[j];                                // sum of bins >= 16t+j
        if (cum >= KDET) { best = t * 16 + j; break; }
    }
    if (best >= 0) atomicMax(&g_B, (unsigned)best);
}

// ---------------- K3: compact keys of candidates in bins >= B ----------------
__global__ void __launch_bounds__(512) k_compact() {
    unsigned i = blockIdx.x * 512 + threadIdx.x;
    unsigned n = min(g_n, (unsigned)ALL_CAP);
    if (i >= n) return;
    unsigned long long key = g_all[i];
    unsigned bits = (unsigned)(key >> 32);
    if ((bits >> 8) - BIN_BASE >= g_B) {
        unsigned pos = atomicAdd(&g_nkeys, 1u);
        if (pos < CAND_CAP) g_keys[pos] = key;
    }
}

// ---------------- K4: sort 1024 keys desc (bitonic), decode top 512 ----------
__global__ void __launch_bounds__(512) k_sortdecode(const float4* __restrict__ loc4,
                                                    const float4* __restrict__ pri4) {
    __shared__ unsigned long long sk[CAND_CAP];
    int t = threadIdx.x;
    unsigned n = min(g_nkeys, (unsigned)CAND_CAP);
    for (int i = t; i < CAND_CAP; i += 512)
        sk[i] = (i < n) ? g_keys[i] : 0ULL;
    __syncthreads();

    for (int k = 2; k <= CAND_CAP; k <<= 1) {
        for (int j = k >> 1; j > 0; j >>= 1) {
            for (int i = t; i < CAND_CAP; i += 512) {
                int ixj = i ^ j;
                if (ixj > i) {
                    unsigned long long a = sk[i], b = sk[ixj];
                    bool desc = ((i & k) == 0);
                    if (desc ? (a < b) : (a > b)) { sk[i] = b; sk[ixj] = a; }
                }
            }
            __syncthreads();
        }
    }

    if (t < KDET) {
        unsigned long long key = sk[t];
        unsigned sb = (unsigned)(key >> 32);
        float4 c = make_float4(0.f, 0.f, 0.f, 0.f);
        float sc = 0.f;
        if (sb) {
            unsigned idx = 0xFFFFFFFFu - (unsigned)(key & 0xFFFFFFFFull);
            float4 l = loc4[idx];
            float4 p = pri4[idx];
            float cx = p.x + (l.x * 0.1f) * p.z;
            float cy = p.y + (l.y * 0.1f) * p.w;
            float w  = p.z * expf(l.z * 0.2f);
            float h  = p.w * expf(l.w * 0.2f);
            float x1 = cx - w * 0.5f;
            float y1 = cy - h * 0.5f;
            float x2 = x1 + w;
            float y2 = y1 + h;
            c = make_float4(x1 * 2048.f, y1 * 2048.f, x2 * 2048.f, y2 * 2048.f);
            sc = __uint_as_float(sb);
        }
        g_cand[t]  = c;
        g_score[t] = sc;
    }
}

// ---------------- K5: 512x512 suppression bitmask -----------------
__global__ void __launch_bounds__(256) k_mask() {
    int w = blockIdx.x * blockDim.x + threadIdx.x;     // 0..8191
    int i = w >> 4, c = w & 15;
    float4 bi = g_cand[i];
    float areai = (bi.z - bi.x + 1.f) * (bi.w - bi.y + 1.f);
    unsigned bits = 0u;
#pragma unroll 4
    for (int b = 0; b < 32; b++) {
        int j = c * 32 + b;
        float4 bj = g_cand[j];
        float areaj = (bj.z - bj.x + 1.f) * (bj.w - bj.y + 1.f);
        float xx1 = fmaxf(bi.x, bj.x), yy1 = fmaxf(bi.y, bj.y);
        float xx2 = fminf(bi.z, bj.z), yy2 = fminf(bi.w, bj.w);
        float ww = fmaxf(xx2 - xx1 + 1.f, 0.f);
        float hh = fmaxf(yy2 - yy1 + 1.f, 0.f);
        float inter = ww * hh;
        float iou = inter / (areai + areaj - inter);
        if (iou > 0.4f && j > i) bits |= (1u << b);
    }
    g_mask[w] = bits;
}

// ---------------- K6: ffs-skip greedy NMS + write output ----------
__global__ void __launch_bounds__(512) k_nms_out(float* __restrict__ out) {
    __shared__ uint4 smask[KDET * 4];                  // 16 words = 4x uint4 per row
    __shared__ unsigned skeep[16];
    int t = threadIdx.x;
    for (int i = t; i < KDET * 4; i += 512)
        smask[i] = ((const uint4*)g_mask)[i];

    bool k0 = g_score[t] > 0.0f;                       // keep0 = top_s > 0
    unsigned wball = __ballot_sync(0xFFFFFFFFu, k0);
    if ((t & 31) == 0) skeep[t >> 5] = wball;
    __syncthreads();

    if (t == 0) {
        unsigned kw[16];
#pragma unroll
        for (int w = 0; w < 16; w++) kw[w] = skeep[w];
#pragma unroll
        for (int w = 0; w < 16; w++) {
            unsigned cur = kw[w];
            while (cur) {
                int bit = __ffs(cur) - 1;
                int i = w * 32 + bit;
                cur &= cur - 1;                        // row i processed
                const uint4* mr = &smask[i * 4];
                uint4 m0 = mr[0], m1 = mr[1], m2 = mr[2], m3 = mr[3];
                kw[0]  &= ~m0.x; kw[1]  &= ~m0.y; kw[2]  &= ~m0.z; kw[3]  &= ~m0.w;
                kw[4]  &= ~m1.x; kw[5]  &= ~m1.y; kw[6]  &= ~m1.z; kw[7]  &= ~m1.w;
                kw[8]  &= ~m2.x; kw[9]  &= ~m2.y; kw[10] &= ~m2.z; kw[11] &= ~m2.w;
                kw[12] &= ~m3.x; kw[13] &= ~m3.y; kw[14] &= ~m3.z; kw[15] &= ~m3.w;
                cur &= kw[w];                          // drop newly suppressed bits
            }
        }
#pragma unroll
        for (int w = 0; w < 16; w++) skeep[w] = kw[w];
    }
    __syncthreads();

    unsigned kept = (skeep[t >> 5] >> (t & 31)) & 1u;
    float4 c = g_cand[t];
    float sc = g_score[t];
    const float inv = 1.0f / 2048.0f;                  // exact (power of 2)
    float o0 = 0.f, o1 = 0.f, o2 = 0.f, o3 = 0.f, o4 = 0.f;
    if (kept) { o0 = c.x * inv; o1 = c.y * inv; o2 = c.z * inv; o3 = c.w * inv; o4 = sc; }
    out[t * 5 + 0] = o0;
    out[t * 5 + 1] = o1;
    out[t * 5 + 2] = o2;
    out[t * 5 + 3] = o3;
    out[t * 5 + 4] = o4;
}

extern "C" void kernel_launch(void* const* d_in, const int* in_sizes, int n_in,
                              void* d_out, int out_size) {
    const float4* loc4  = (const float4*)d_in[0];
    const float4* conf4 = (const float4*)d_in[1];
    const float4* pri4  = (const float4*)d_in[2];
    float* out = (float*)d_out;

    int nElem  = in_sizes[1] / 2;                   // N priors
    int nPairs = (nElem + 1) / 2;                   // float4 count of conf
    int scanBlocks = (nPairs + 2047) / 2048;        // 4 float4 per thread, 512 thr

    k_zero<<<(NBINS + 511) / 512, 512>>>();
    k_scan<<<scanBlocks, 512>>>(conf4, nPairs);
    k_select<<<1, 512>>>();
    k_compact<<<ALL_CAP / 512, 512>>>();
    k_sortdecode<<<1, 512>>>(loc4, pri4);
    k_mask<<<(KDET * 16) / 256, 256>>>();
    k_nms_out<<<1, 512>>>(out);
}